// round 2
// baseline (speedup 1.0000x reference)
#include <cuda_runtime.h>
#include <cuda_bf16.h>
#include <math.h>

#define N_ITER 32768
#define NB 257
#define PIANO 8388608
#define CHUNK 64
#define WARM 20

// Frequency-domain scratch (static __device__ arrays — no allocs allowed).
__device__ float g_ehr[N_ITER * NB];
__device__ float g_ehi[N_ITER * NB];
__device__ float g_zr[N_ITER * NB];
__device__ float g_zi[N_ITER * NB];

__device__ __forceinline__ float2 cmulf(float2 a, float2 b) {
    return make_float2(a.x * b.x - a.y * b.y, a.x * b.y + a.y * b.x);
}

// ---------------------------------------------------------------------------
// Kernel 1: impulse generation + 512-point real FFT (as 256-pt complex
// Stockham radix-2 + real-FFT untangle). One frame per CTA, 128 threads.
// ---------------------------------------------------------------------------
__global__ void __launch_bounds__(128) fwd_kernel(const float* __restrict__ noise,
                                                  const float* __restrict__ env) {
    __shared__ float2 buf[2][256];
    int f = blockIdx.x, t = threadIdx.x;
    float e = env[f];
    float amp = e * e;
    const float* nf = noise + (size_t)f * 512;

    // Pack imp[2n] + i*imp[2n+1] into 256 complex values.
    {
        float4 v = ((const float4*)nf)[t];  // floats 4t..4t+3
        buf[0][2 * t]     = make_float2((2.f * v.x - 1.f) * amp, (2.f * v.y - 1.f) * amp);
        buf[0][2 * t + 1] = make_float2((2.f * v.z - 1.f) * amp, (2.f * v.w - 1.f) * amp);
    }
    __syncthreads();

    int p = 0;
#pragma unroll
    for (int s = 0; s < 8; ++s) {
        int m = 1 << s;
        int l = 128 >> s;
        int j = t >> s;
        int k = t & (m - 1);
        float2 c0 = buf[p][t];
        float2 c1 = buf[p][t + 128];
        float2 su = make_float2(c0.x + c1.x, c0.y + c1.y);
        float2 df = make_float2(c0.x - c1.x, c0.y - c1.y);
        float sn, cs;
        sincospif(-(float)j / (float)l, &sn, &cs);  // e^{-i*pi*j/l}
        float2 tw = make_float2(df.x * cs - df.y * sn, df.x * sn + df.y * cs);
        buf[p ^ 1][2 * (t - k) + k]     = su;
        buf[p ^ 1][2 * (t - k) + k + m] = tw;
        p ^= 1;
        __syncthreads();
    }

    // Untangle 256-pt complex FFT Z into 257-bin rfft X.
    float* ehr = g_ehr + (size_t)f * NB;
    float* ehi = g_ehi + (size_t)f * NB;
#pragma unroll
    for (int h = 0; h < 2; ++h) {
        int k = t + 128 * h;
        float2 A = buf[p][k];
        float2 C = buf[p][(256 - k) & 255];
        float2 B = make_float2(C.x, -C.y);
        float2 Xe = make_float2(0.5f * (A.x + B.x), 0.5f * (A.y + B.y));
        float2 D  = make_float2(0.5f * (A.x - B.x), 0.5f * (A.y - B.y));
        float2 Xo = make_float2(D.y, -D.x);  // -i*D
        float sn, cs;
        sincospif(-(float)k / 256.f, &sn, &cs);  // e^{-2*pi*i*k/512}
        float2 X = cmulf(make_float2(cs, sn), Xo);
        X.x += Xe.x;
        X.y += Xe.y;
        ehr[k] = X.x;
        ehi[k] = X.y;
    }
    if (t == 0) {
        float2 Z0 = buf[p][0];
        ehr[256] = Z0.x - Z0.y;
        ehi[256] = 0.f;
    }
}

// ---------------------------------------------------------------------------
// Kernel 2: chunk-parallel frequency-domain recurrence.
//   y_i = T * P(tf_i .* (y_{i-1} + ehat_i)),  z_i = y_{i-1} + ehat_i stored.
// T tridiagonal circulant (0.54, -0.23, -0.23) with Hermitian wrap at bins
// 0 and 256; P zeroes imag at bins 0 / 256 (irfft semantics).
// Contraction |tf| <= 0.283 lets each chunk warm up from zero in WARM steps.
// 288 threads (9 warps), bin k = tid for tid < 257.
// ---------------------------------------------------------------------------
__global__ void __launch_bounds__(288) recur_kernel(const float* __restrict__ tfr_g,
                                                    const float* __restrict__ tfi_g) {
    __shared__ float2 gbuf[2][260];
    int c = blockIdx.x, t = threadIdx.x;
    int start = c * CHUNK;
    int i0 = start - WARM;
    if (i0 < 0) i0 = 0;
    int end = start + CHUNK;
    bool act = (t < NB);
    int k = act ? t : 0;

    float yr = 0.f, yi = 0.f;
    float er = 0.f, ei = 0.f, tr = 0.f, ti = 0.f;
    if (act) {
        size_t b = (size_t)i0 * NB + k;
        er = g_ehr[b]; ei = g_ehi[b];
        tr = tfr_g[b]; ti = tfi_g[b];
    }
    int p = 0;
    for (int i = i0; i < end; ++i) {
        float cer = er, cei = ei, ctr = tr, cti = ti;
        if (act && (i + 1 < end)) {  // prefetch next frame (independent of y)
            size_t b2 = (size_t)(i + 1) * NB + k;
            er = g_ehr[b2]; ei = g_ehi[b2];
            tr = tfr_g[b2]; ti = tfi_g[b2];
        }
        float zr = yr + cer, zi = yi + cei;
        if (act && i >= start) {
            size_t bo = (size_t)i * NB + k;
            g_zr[bo] = zr;
            g_zi[bo] = zi;
        }
        float gr = ctr * zr - cti * zi;
        float gi = ctr * zi + cti * zr;
        if (k == 0 || k == 256) gi = 0.f;  // P: irfft drops imag at DC/Nyquist
        if (act) {
            gbuf[p][k + 1] = make_float2(gr, gi);
            if (k == 1)   gbuf[p][0]   = make_float2(gr, -gi);  // g[-1]  = conj(g[1])
            if (k == 255) gbuf[p][258] = make_float2(gr, -gi);  // g[257] = conj(g[255])
        }
        __syncthreads();
        if (act) {
            float2 L = gbuf[p][k];
            float2 R = gbuf[p][k + 2];
            yr = 0.54f * gr - 0.23f * (L.x + R.x);
            yi = 0.54f * gi - 0.23f * (L.y + R.y);
        }
        p ^= 1;
    }
}

// ---------------------------------------------------------------------------
// Kernels 3/4: batched 512-pt irfft of z spectra + overlap-add (hop 256).
// Even frames tile [0, PIANO) exactly -> write; odd frames -> disjoint RMW add.
// One frame per CTA, 128 threads.
// ---------------------------------------------------------------------------
__global__ void __launch_bounds__(128) inv_kernel(float* __restrict__ out, int parity) {
    __shared__ float2 buf[2][256];
    __shared__ float2 Xs[257];
    int f = 2 * blockIdx.x + parity;
    int t = threadIdx.x;
    const float* zr = g_zr + (size_t)f * NB;
    const float* zi = g_zi + (size_t)f * NB;
    Xs[t]       = make_float2(zr[t], zi[t]);
    Xs[t + 128] = make_float2(zr[t + 128], zi[t + 128]);
    if (t == 0) Xs[256] = make_float2(zr[256], zi[256]);
    __syncthreads();

    // Inverse untangle: Z[k] = Xe[k] + i*Xo[k], scaled by 1/256.
#pragma unroll
    for (int h = 0; h < 2; ++h) {
        int k = t + 128 * h;
        float2 A = Xs[k];
        float2 C = Xs[256 - k];
        float2 B = make_float2(C.x, -C.y);
        float2 Xe = make_float2(0.5f * (A.x + B.x), 0.5f * (A.y + B.y));
        float2 D  = make_float2(0.5f * (A.x - B.x), 0.5f * (A.y - B.y));
        float sn, cs;
        sincospif((float)k / 256.f, &sn, &cs);  // e^{+2*pi*i*k/512}
        float2 Xo = make_float2(D.x * cs - D.y * sn, D.x * sn + D.y * cs);
        buf[0][k] = make_float2((Xe.x - Xo.y) * (1.f / 256.f),
                                (Xe.y + Xo.x) * (1.f / 256.f));
    }
    __syncthreads();

    int p = 0;
#pragma unroll
    for (int s = 0; s < 8; ++s) {
        int m = 1 << s;
        int l = 128 >> s;
        int j = t >> s;
        int k = t & (m - 1);
        float2 c0 = buf[p][t];
        float2 c1 = buf[p][t + 128];
        float2 su = make_float2(c0.x + c1.x, c0.y + c1.y);
        float2 df = make_float2(c0.x - c1.x, c0.y - c1.y);
        float sn, cs;
        sincospif((float)j / (float)l, &sn, &cs);  // conjugate twiddle (inverse)
        float2 tw = make_float2(df.x * cs - df.y * sn, df.x * sn + df.y * cs);
        buf[p ^ 1][2 * (t - k) + k]     = su;
        buf[p ^ 1][2 * (t - k) + k + m] = tw;
        p ^= 1;
        __syncthreads();
    }

    // buf[p][n] = x[2n] + i*x[2n+1]; overlap-add at offset f*256.
    size_t base = (size_t)f * 256;
    float2* o2 = (float2*)(out + base);
#pragma unroll
    for (int h = 0; h < 2; ++h) {
        int n = t + 128 * h;
        float2 v = buf[p][n];
        if (parity == 0) {
            o2[n] = v;
        } else {
            if (base + 2 * (size_t)n + 1 < (size_t)PIANO) {
                float2 cur = o2[n];
                o2[n] = make_float2(cur.x + v.x, cur.y + v.y);
            }
        }
    }
}

// ---------------------------------------------------------------------------
extern "C" void kernel_launch(void* const* d_in, const int* in_sizes, int n_in,
                              void* d_out, int out_size) {
    const float* noise = nullptr;
    const float* env = nullptr;
    const float* tfr = nullptr;
    const float* tfi = nullptr;
    for (int i = 0; i < n_in; ++i) {
        if (in_sizes[i] == 16777216) noise = (const float*)d_in[i];          // [32768, 512]
        else if (in_sizes[i] == 32770) env = (const float*)d_in[i];          // [32770]
        else if (in_sizes[i] == 8421890) {                                   // [32770, 257] x2
            if (!tfr) tfr = (const float*)d_in[i];
            else      tfi = (const float*)d_in[i];
        }
    }
    float* out = (float*)d_out;

    fwd_kernel<<<N_ITER, 128>>>(noise, env);
    recur_kernel<<<N_ITER / CHUNK, 288>>>(tfr, tfi);
    inv_kernel<<<N_ITER / 2, 128>>>(out, 0);
    inv_kernel<<<N_ITER / 2, 128>>>(out, 1);
}

// round 4
// speedup vs baseline: 1.2993x; 1.2993x over previous
#include <cuda_runtime.h>
#include <cuda_bf16.h>
#include <math.h>

#define N_ITER 32768
#define NB 257
#define PIANO 8388608
#define CHUNK 32
#define WARM 12

// padded shared index: break 32-float bank periodicity
#define SP(i) ((i) + ((i) >> 5))

// Frequency-domain scratch (static __device__ arrays — no allocs allowed).
__device__ float g_ehr[N_ITER * NB];
__device__ float g_ehi[N_ITER * NB];
__device__ float g_zr[N_ITER * NB];
__device__ float g_zi[N_ITER * NB];

// ---------------------------------------------------------------------------
// Kernel 1: impulse generation + 512-pt real FFT as 256-pt complex radix-4
// Stockham (4 stages) + real-FFT untangle. One frame per CTA, 64 threads.
// ---------------------------------------------------------------------------
__global__ void __launch_bounds__(64) fwd_kernel(const float* __restrict__ noise,
                                                 const float* __restrict__ env) {
    __shared__ float sre[2][264], sim[2][264];
    __shared__ float twc[257], tws[257];   // tw[k] = e^{-i*pi*k/256}
    int f = blockIdx.x, t = threadIdx.x;

    for (int k = t; k < 257; k += 64) {
        float s, c;
        sincospif(-(float)k / 256.f, &s, &c);
        twc[k] = c; tws[k] = s;
    }

    float e = env[f];
    float amp = e * e;
    const float4* nf = (const float4*)(noise + (size_t)f * 512);
    float4 v0 = nf[2 * t];
    float4 v1 = nf[2 * t + 1];
    // pack imp[2n] + i*imp[2n+1]
    sre[0][SP(4 * t + 0)] = (2.f * v0.x - 1.f) * amp;
    sim[0][SP(4 * t + 0)] = (2.f * v0.y - 1.f) * amp;
    sre[0][SP(4 * t + 1)] = (2.f * v0.z - 1.f) * amp;
    sim[0][SP(4 * t + 1)] = (2.f * v0.w - 1.f) * amp;
    sre[0][SP(4 * t + 2)] = (2.f * v1.x - 1.f) * amp;
    sim[0][SP(4 * t + 2)] = (2.f * v1.y - 1.f) * amp;
    sre[0][SP(4 * t + 3)] = (2.f * v1.z - 1.f) * amp;
    sim[0][SP(4 * t + 3)] = (2.f * v1.w - 1.f) * amp;
    __syncthreads();

    int p = 0;
#pragma unroll
    for (int r = 0; r < 4; ++r) {
        int m = 1 << (2 * r);
        int k = t & (m - 1);
        int j = t >> (2 * r);
        float x0r = sre[p][SP(t)],       x0i = sim[p][SP(t)];
        float x1r = sre[p][SP(t + 64)],  x1i = sim[p][SP(t + 64)];
        float x2r = sre[p][SP(t + 128)], x2i = sim[p][SP(t + 128)];
        float x3r = sre[p][SP(t + 192)], x3i = sim[p][SP(t + 192)];
        float t0r = x0r + x2r, t0i = x0i + x2i;
        float t1r = x0r - x2r, t1i = x0i - x2i;
        float t2r = x1r + x3r, t2i = x1i + x3i;
        float t3r = x1r - x3r, t3i = x1i - x3i;
        float y0r = t0r + t2r, y0i = t0i + t2i;
        float u1r = t1r + t3i, u1i = t1i - t3r;   // t1 - i*t3
        float u2r = t0r - t2r, u2i = t0i - t2i;
        float u3r = t1r - t3i, u3i = t1i + t3r;   // t1 + i*t3
        int idx = 2 * j * m;                       // W^{jm} = tw[2jm]
        float w1c = twc[idx], w1s = tws[idx];
        float w2c = w1c * w1c - w1s * w1s, w2s = 2.f * w1c * w1s;
        float w3c = w2c * w1c - w2s * w1s, w3s = w2c * w1s + w2s * w1c;
        int o = 4 * m * j + k;
        int q = p ^ 1;
        sre[q][SP(o)]         = y0r;
        sim[q][SP(o)]         = y0i;
        sre[q][SP(o + m)]     = u1r * w1c - u1i * w1s;
        sim[q][SP(o + m)]     = u1r * w1s + u1i * w1c;
        sre[q][SP(o + 2 * m)] = u2r * w2c - u2i * w2s;
        sim[q][SP(o + 2 * m)] = u2r * w2s + u2i * w2c;
        sre[q][SP(o + 3 * m)] = u3r * w3c - u3i * w3s;
        sim[q][SP(o + 3 * m)] = u3r * w3s + u3i * w3c;
        p = q;
        __syncthreads();
    }

    // Untangle 256-pt complex FFT Z into 257-bin rfft X.
    float* ehr = g_ehr + (size_t)f * NB;
    float* ehi = g_ehi + (size_t)f * NB;
#pragma unroll
    for (int h = 0; h < 4; ++h) {
        int k = t + 64 * h;
        int k2 = (256 - k) & 255;
        float Ar = sre[p][SP(k)],  Ai = sim[p][SP(k)];
        float Cr = sre[p][SP(k2)], Ci = sim[p][SP(k2)];
        float Xer = 0.5f * (Ar + Cr), Xei = 0.5f * (Ai - Ci);
        float Dr  = 0.5f * (Ar - Cr), Di  = 0.5f * (Ai + Ci);
        float Xor = Di, Xoi = -Dr;                 // -i*D
        float c = twc[k], s = tws[k];
        ehr[k] = Xer + Xor * c - Xoi * s;
        ehi[k] = Xei + Xor * s + Xoi * c;
    }
    if (t == 0) {
        ehr[256] = sre[p][SP(0)] - sim[p][SP(0)];
        ehi[256] = 0.f;
    }
}

// ---------------------------------------------------------------------------
// Kernel 2: chunk-parallel frequency-domain recurrence.
//   y_i = T * P(tf_i .* (y_{i-1} + ehat_i)),  z_i = y_{i-1} + ehat_i stored.
// T tridiagonal circulant (0.54, -0.23, -0.23); contraction |tf|<=0.283 lets
// each chunk warm up from zero in WARM steps (0.283^12 ~ 3e-7).
// ---------------------------------------------------------------------------
__global__ void __launch_bounds__(288) recur_kernel(const float* __restrict__ tfr_g,
                                                    const float* __restrict__ tfi_g) {
    __shared__ float2 gbuf[2][260];
    int c = blockIdx.x, t = threadIdx.x;
    int start = c * CHUNK;
    int i0 = start - WARM;
    if (i0 < 0) i0 = 0;
    int end = start + CHUNK;
    bool act = (t < NB);
    int k = act ? t : 0;

    float yr = 0.f, yi = 0.f;
    float er = 0.f, ei = 0.f, tr = 0.f, ti = 0.f;
    if (act) {
        size_t b = (size_t)i0 * NB + k;
        er = g_ehr[b]; ei = g_ehi[b];
        tr = tfr_g[b]; ti = tfi_g[b];
    }
    int p = 0;
    for (int i = i0; i < end; ++i) {
        float cer = er, cei = ei, ctr = tr, cti = ti;
        if (act && (i + 1 < end)) {  // prefetch next frame (independent of y)
            size_t b2 = (size_t)(i + 1) * NB + k;
            er = g_ehr[b2]; ei = g_ehi[b2];
            tr = tfr_g[b2]; ti = tfi_g[b2];
        }
        float zr = yr + cer, zi = yi + cei;
        if (act && i >= start) {
            size_t bo = (size_t)i * NB + k;
            g_zr[bo] = zr;
            g_zi[bo] = zi;
        }
        float gr = ctr * zr - cti * zi;
        float gi = ctr * zi + cti * zr;
        if (k == 0 || k == 256) gi = 0.f;  // P: irfft drops imag at DC/Nyquist
        if (act) {
            gbuf[p][k + 1] = make_float2(gr, gi);
            if (k == 1)   gbuf[p][0]   = make_float2(gr, -gi);  // g[-1]  = conj(g[1])
            if (k == 255) gbuf[p][258] = make_float2(gr, -gi);  // g[257] = conj(g[255])
        }
        __syncthreads();
        if (act) {
            float2 L = gbuf[p][k];
            float2 R = gbuf[p][k + 2];
            yr = 0.54f * gr - 0.23f * (L.x + R.x);
            yi = 0.54f * gi - 0.23f * (L.y + R.y);
        }
        p ^= 1;
    }
}

// ---------------------------------------------------------------------------
// Kernels 3/4: batched 512-pt irfft (radix-4) + overlap-add (hop 256).
// Even frames tile output exactly -> write; odd frames -> disjoint RMW add.
// One frame per CTA, 64 threads.
// ---------------------------------------------------------------------------
__global__ void __launch_bounds__(64) inv_kernel(float* __restrict__ out, int parity) {
    __shared__ float sre[2][264], sim[2][264];
    __shared__ float Xr_[257], Xi_[257];
    __shared__ float twc[257], tws[257];   // tw[k] = e^{-i*pi*k/256}
    int f = 2 * blockIdx.x + parity;
    int t = threadIdx.x;

    for (int k = t; k < 257; k += 64) {
        float s, c;
        sincospif(-(float)k / 256.f, &s, &c);
        twc[k] = c; tws[k] = s;
    }

    const float* zr = g_zr + (size_t)f * NB;
    const float* zi = g_zi + (size_t)f * NB;
#pragma unroll
    for (int h = 0; h < 4; ++h) {
        int k = t + 64 * h;
        Xr_[k] = zr[k];
        Xi_[k] = zi[k];
    }
    if (t == 0) { Xr_[256] = zr[256]; Xi_[256] = zi[256]; }
    __syncthreads();

    // Inverse untangle: Z[k] = (Xe + i*Xo)/256, Xo = e^{+i*pi*k/256} * D
#pragma unroll
    for (int h = 0; h < 4; ++h) {
        int k = t + 64 * h;
        float Ar = Xr_[k],       Ai = Xi_[k];
        float Cr = Xr_[256 - k], Ci = Xi_[256 - k];
        float Xer = 0.5f * (Ar + Cr), Xei = 0.5f * (Ai - Ci);
        float Dr  = 0.5f * (Ar - Cr), Di  = 0.5f * (Ai + Ci);
        float c = twc[k], s = -tws[k];            // conj table = e^{+i...}
        float Xor = Dr * c - Di * s;
        float Xoi = Dr * s + Di * c;
        sre[0][SP(k)] = (Xer - Xoi) * (1.f / 256.f);
        sim[0][SP(k)] = (Xei + Xor) * (1.f / 256.f);
    }
    __syncthreads();

    int p = 0;
#pragma unroll
    for (int r = 0; r < 4; ++r) {
        int m = 1 << (2 * r);
        int k = t & (m - 1);
        int j = t >> (2 * r);
        float x0r = sre[p][SP(t)],       x0i = sim[p][SP(t)];
        float x1r = sre[p][SP(t + 64)],  x1i = sim[p][SP(t + 64)];
        float x2r = sre[p][SP(t + 128)], x2i = sim[p][SP(t + 128)];
        float x3r = sre[p][SP(t + 192)], x3i = sim[p][SP(t + 192)];
        float t0r = x0r + x2r, t0i = x0i + x2i;
        float t1r = x0r - x2r, t1i = x0i - x2i;
        float t2r = x1r + x3r, t2i = x1i + x3i;
        float t3r = x1r - x3r, t3i = x1i - x3i;
        float y0r = t0r + t2r, y0i = t0i + t2i;
        float u1r = t1r - t3i, u1i = t1i + t3r;   // t1 + i*t3 (inverse)
        float u2r = t0r - t2r, u2i = t0i - t2i;
        float u3r = t1r + t3i, u3i = t1i - t3r;   // t1 - i*t3 (inverse)
        int idx = 2 * j * m;
        float w1c = twc[idx], w1s = -tws[idx];    // conj twiddle
        float w2c = w1c * w1c - w1s * w1s, w2s = 2.f * w1c * w1s;
        float w3c = w2c * w1c - w2s * w1s, w3s = w2c * w1s + w2s * w1c;
        int o = 4 * m * j + k;
        int q = p ^ 1;
        sre[q][SP(o)]         = y0r;
        sim[q][SP(o)]         = y0i;
        sre[q][SP(o + m)]     = u1r * w1c - u1i * w1s;
        sim[q][SP(o + m)]     = u1r * w1s + u1i * w1c;
        sre[q][SP(o + 2 * m)] = u2r * w2c - u2i * w2s;
        sim[q][SP(o + 2 * m)] = u2r * w2s + u2i * w2c;
        sre[q][SP(o + 3 * m)] = u3r * w3c - u3i * w3s;
        sim[q][SP(o + 3 * m)] = u3r * w3s + u3i * w3c;
        p = q;
        __syncthreads();
    }

    // buf[n] = x[2n] + i*x[2n+1]; overlap-add at offset f*256.
    size_t base = (size_t)f * 256;
    float2* o2 = (float2*)(out + base);
#pragma unroll
    for (int h = 0; h < 4; ++h) {
        int n = t + 64 * h;
        float2 v = make_float2(sre[p][SP(n)], sim[p][SP(n)]);
        if (parity == 0) {
            o2[n] = v;
        } else {
            if (base + 2 * (size_t)n + 1 < (size_t)PIANO) {
                float2 cur = o2[n];
                o2[n] = make_float2(cur.x + v.x, cur.y + v.y);
            }
        }
    }
}

// ---------------------------------------------------------------------------
extern "C" void kernel_launch(void* const* d_in, const int* in_sizes, int n_in,
                              void* d_out, int out_size) {
    const float* noise = nullptr;
    const float* env = nullptr;
    const float* tfr = nullptr;
    const float* tfi = nullptr;
    for (int i = 0; i < n_in; ++i) {
        if (in_sizes[i] == 16777216) noise = (const float*)d_in[i];          // [32768, 512]
        else if (in_sizes[i] == 32770) env = (const float*)d_in[i];          // [32770]
        else if (in_sizes[i] == 8421890) {                                   // [32770, 257] x2
            if (!tfr) tfr = (const float*)d_in[i];
            else      tfi = (const float*)d_in[i];
        }
    }
    float* out = (float*)d_out;

    fwd_kernel<<<N_ITER, 64>>>(noise, env);
    recur_kernel<<<N_ITER / CHUNK, 288>>>(tfr, tfi);
    inv_kernel<<<N_ITER / 2, 64>>>(out, 0);
    inv_kernel<<<N_ITER / 2, 64>>>(out, 1);
}

// round 6
// speedup vs baseline: 1.3090x; 1.0074x over previous
#include <cuda_runtime.h>
#include <cuda_bf16.h>
#include <math.h>

#define N_ITER 32768
#define NB 257
#define PIANO 8388608
#define CHUNK 32
#define WARM 12
#define FPB 4   // frames per CTA (256 threads = 4 groups of 64)

// padded shared index: break 32-float bank periodicity
#define SP(i) ((i) + ((i) >> 5))

// Frequency-domain scratch (static __device__ arrays — no allocs allowed).
__device__ float g_ehr[N_ITER * NB];
__device__ float g_ehi[N_ITER * NB];
__device__ float g_zr[N_ITER * NB];
__device__ float g_zi[N_ITER * NB];
__device__ float g_twc[257], g_tws[257];   // e^{-i*pi*k/256}

__global__ void tw_init_kernel() {
    int k = threadIdx.x;
    if (k < 257) {
        float s, c;
        sincospif(-(float)k / 256.f, &s, &c);
        g_twc[k] = c; g_tws[k] = s;
    }
}

// ---------------------------------------------------------------------------
// Kernel 1: impulse gen + 512-pt real FFT as 256-pt complex radix-4 Stockham.
// Stage 0 fused with the global load (registers); stage 3 is twiddle-free.
// 4 frames per 256-thread CTA; 64 threads per frame.
// ---------------------------------------------------------------------------
__global__ void __launch_bounds__(256) fwd_kernel(const float* __restrict__ noise,
                                                  const float* __restrict__ env) {
    __shared__ float Ar[FPB][264], Ai[FPB][264], Br[FPB][264], Bi[FPB][264];
    __shared__ float twc[257], tws[257];
    int t = threadIdx.x & 63, g = threadIdx.x >> 6;
    int f = blockIdx.x * FPB + g;

    { int k = threadIdx.x;
      twc[k] = g_twc[k]; tws[k] = g_tws[k];
      if (k == 0) { twc[256] = g_twc[256]; tws[256] = g_tws[256]; } }

    // Load packed input x[n] = imp[2n] + i*imp[2n+1] at n = t + 64j (regs).
    float e = env[f];
    float amp = e * e;
    const float2* nf2 = (const float2*)(noise + (size_t)f * 512);
    float x0r, x0i, x1r, x1i, x2r, x2i, x3r, x3i;
    { float2 v = nf2[t];       x0r = (2.f*v.x-1.f)*amp; x0i = (2.f*v.y-1.f)*amp; }
    { float2 v = nf2[t + 64];  x1r = (2.f*v.x-1.f)*amp; x1i = (2.f*v.y-1.f)*amp; }
    { float2 v = nf2[t + 128]; x2r = (2.f*v.x-1.f)*amp; x2i = (2.f*v.y-1.f)*amp; }
    { float2 v = nf2[t + 192]; x3r = (2.f*v.x-1.f)*amp; x3i = (2.f*v.y-1.f)*amp; }
    __syncthreads();   // table ready

    // Stage 0 (m=1, j=t) in registers -> A.
    {
        float t0r = x0r + x2r, t0i = x0i + x2i;
        float t1r = x0r - x2r, t1i = x0i - x2i;
        float t2r = x1r + x3r, t2i = x1i + x3i;
        float t3r = x1r - x3r, t3i = x1i - x3i;
        float y0r = t0r + t2r, y0i = t0i + t2i;
        float u1r = t1r + t3i, u1i = t1i - t3r;
        float u2r = t0r - t2r, u2i = t0i - t2i;
        float u3r = t1r - t3i, u3i = t1i + t3r;
        float w1c = twc[2 * t], w1s = tws[2 * t];
        float w2c = w1c*w1c - w1s*w1s, w2s = 2.f*w1c*w1s;
        float w3c = w2c*w1c - w2s*w1s, w3s = w2c*w1s + w2s*w1c;
        int o = 4 * t;
        Ar[g][SP(o)]   = y0r;                  Ai[g][SP(o)]   = y0i;
        Ar[g][SP(o+1)] = u1r*w1c - u1i*w1s;    Ai[g][SP(o+1)] = u1r*w1s + u1i*w1c;
        Ar[g][SP(o+2)] = u2r*w2c - u2i*w2s;    Ai[g][SP(o+2)] = u2r*w2s + u2i*w2c;
        Ar[g][SP(o+3)] = u3r*w3c - u3i*w3s;    Ai[g][SP(o+3)] = u3r*w3s + u3i*w3c;
    }
    __syncthreads();

    // Stages 1-2 through shared (A->B->A).
#pragma unroll
    for (int r = 1; r < 3; ++r) {
        int m = 1 << (2 * r);
        int k = t & (m - 1);
        int j = t >> (2 * r);
        const float (*srcr)[264] = (r == 1) ? Ar : Br;
        const float (*srci)[264] = (r == 1) ? Ai : Bi;
        float (*dstr)[264] = (r == 1) ? Br : Ar;
        float (*dsti)[264] = (r == 1) ? Bi : Ai;
        float a0r = srcr[g][SP(t)],       a0i = srci[g][SP(t)];
        float a1r = srcr[g][SP(t + 64)],  a1i = srci[g][SP(t + 64)];
        float a2r = srcr[g][SP(t + 128)], a2i = srci[g][SP(t + 128)];
        float a3r = srcr[g][SP(t + 192)], a3i = srci[g][SP(t + 192)];
        float t0r = a0r + a2r, t0i = a0i + a2i;
        float t1r = a0r - a2r, t1i = a0i - a2i;
        float t2r = a1r + a3r, t2i = a1i + a3i;
        float t3r = a1r - a3r, t3i = a1i - a3i;
        float y0r = t0r + t2r, y0i = t0i + t2i;
        float u1r = t1r + t3i, u1i = t1i - t3r;
        float u2r = t0r - t2r, u2i = t0i - t2i;
        float u3r = t1r - t3i, u3i = t1i + t3r;
        int idx = 2 * j * m;
        float w1c = twc[idx], w1s = tws[idx];
        float w2c = w1c*w1c - w1s*w1s, w2s = 2.f*w1c*w1s;
        float w3c = w2c*w1c - w2s*w1s, w3s = w2c*w1s + w2s*w1c;
        int o = 4 * m * j + k;
        dstr[g][SP(o)]       = y0r;                  dsti[g][SP(o)]       = y0i;
        dstr[g][SP(o+m)]     = u1r*w1c - u1i*w1s;    dsti[g][SP(o+m)]     = u1r*w1s + u1i*w1c;
        dstr[g][SP(o+2*m)]   = u2r*w2c - u2i*w2s;    dsti[g][SP(o+2*m)]   = u2r*w2s + u2i*w2c;
        dstr[g][SP(o+3*m)]   = u3r*w3c - u3i*w3s;    dsti[g][SP(o+3*m)]   = u3r*w3s + u3i*w3c;
        __syncthreads();
    }

    // Stage 3 (m=64, j=0: all twiddles = 1) -> Z[t+64h] stored unpadded in B.
    {
        float a0r = Ar[g][SP(t)],       a0i = Ai[g][SP(t)];
        float a1r = Ar[g][SP(t + 64)],  a1i = Ai[g][SP(t + 64)];
        float a2r = Ar[g][SP(t + 128)], a2i = Ai[g][SP(t + 128)];
        float a3r = Ar[g][SP(t + 192)], a3i = Ai[g][SP(t + 192)];
        float t0r = a0r + a2r, t0i = a0i + a2i;
        float t1r = a0r - a2r, t1i = a0i - a2i;
        float t2r = a1r + a3r, t2i = a1i + a3i;
        float t3r = a1r - a3r, t3i = a1i - a3i;
        Br[g][t]       = t0r + t2r;  Bi[g][t]       = t0i + t2i;
        Br[g][t + 64]  = t1r + t3i;  Bi[g][t + 64]  = t1i - t3r;
        Br[g][t + 128] = t0r - t2r;  Bi[g][t + 128] = t0i - t2i;
        Br[g][t + 192] = t1r - t3i;  Bi[g][t + 192] = t1i + t3r;
    }
    __syncthreads();

    // Untangle 256-pt complex FFT Z into 257-bin rfft.
    float* ehr = g_ehr + (size_t)f * NB;
    float* ehi = g_ehi + (size_t)f * NB;
#pragma unroll
    for (int h = 0; h < 4; ++h) {
        int k = t + 64 * h;
        int k2 = (256 - k) & 255;
        float Arv = Br[g][k],  Aiv = Bi[g][k];
        float Crv = Br[g][k2], Civ = Bi[g][k2];
        float Xer = 0.5f * (Arv + Crv), Xei = 0.5f * (Aiv - Civ);
        float Dr  = 0.5f * (Arv - Crv), Di  = 0.5f * (Aiv + Civ);
        float Xor = Di, Xoi = -Dr;                 // -i*D
        float c = twc[k], s = tws[k];
        ehr[k] = Xer + Xor * c - Xoi * s;
        ehi[k] = Xei + Xor * s + Xoi * c;
    }
    if (t == 0) {
        ehr[256] = Br[g][0] - Bi[g][0];
        ehi[256] = 0.f;
    }
}

// ---------------------------------------------------------------------------
// Kernel 2: chunk-parallel frequency-domain recurrence (unchanged).
// ---------------------------------------------------------------------------
__global__ void __launch_bounds__(288) recur_kernel(const float* __restrict__ tfr_g,
                                                    const float* __restrict__ tfi_g) {
    __shared__ float2 gbuf[2][260];
    int c = blockIdx.x, t = threadIdx.x;
    int start = c * CHUNK;
    int i0 = start - WARM;
    if (i0 < 0) i0 = 0;
    int end = start + CHUNK;
    bool act = (t < NB);
    int k = act ? t : 0;

    float yr = 0.f, yi = 0.f;
    float er = 0.f, ei = 0.f, tr = 0.f, ti = 0.f;
    if (act) {
        size_t b = (size_t)i0 * NB + k;
        er = g_ehr[b]; ei = g_ehi[b];
        tr = tfr_g[b]; ti = tfi_g[b];
    }
    int p = 0;
    for (int i = i0; i < end; ++i) {
        float cer = er, cei = ei, ctr = tr, cti = ti;
        if (act && (i + 1 < end)) {
            size_t b2 = (size_t)(i + 1) * NB + k;
            er = g_ehr[b2]; ei = g_ehi[b2];
            tr = tfr_g[b2]; ti = tfi_g[b2];
        }
        float zr = yr + cer, zi = yi + cei;
        if (act && i >= start) {
            size_t bo = (size_t)i * NB + k;
            g_zr[bo] = zr;
            g_zi[bo] = zi;
        }
        float gr = ctr * zr - cti * zi;
        float gi = ctr * zi + cti * zr;
        if (k == 0 || k == 256) gi = 0.f;
        if (act) {
            gbuf[p][k + 1] = make_float2(gr, gi);
            if (k == 1)   gbuf[p][0]   = make_float2(gr, -gi);
            if (k == 255) gbuf[p][258] = make_float2(gr, -gi);
        }
        __syncthreads();
        if (act) {
            float2 L = gbuf[p][k];
            float2 R = gbuf[p][k + 2];
            yr = 0.54f * gr - 0.23f * (L.x + R.x);
            yi = 0.54f * gi - 0.23f * (L.y + R.y);
        }
        p ^= 1;
    }
}

// ---------------------------------------------------------------------------
// Kernels 3/4: batched 512-pt irfft + overlap-add. Untangle+stage0 fused in
// registers; stage 3 is twiddle-free and writes straight to global (coalesced).
// 4 frames per 256-thread CTA.
// ---------------------------------------------------------------------------
__global__ void __launch_bounds__(256) inv_kernel(float* __restrict__ out, int parity) {
    __shared__ float Ar[FPB][264], Ai[FPB][264], Br[FPB][264], Bi[FPB][264];
    __shared__ float twc[257], tws[257];
    int t = threadIdx.x & 63, g = threadIdx.x >> 6;
    int f = (blockIdx.x * FPB + g) * 2 + parity;

    { int k = threadIdx.x;
      twc[k] = g_twc[k]; tws[k] = g_tws[k];
      if (k == 0) { twc[256] = g_twc[256]; tws[256] = g_tws[256]; } }

    // Stage z spectrum (257 entries) into B (unpadded).
    const float* zr = g_zr + (size_t)f * NB;
    const float* zi = g_zi + (size_t)f * NB;
    for (int k = t; k < 257; k += 64) { Br[g][k] = zr[k]; Bi[g][k] = zi[k]; }
    __syncthreads();

    // Untangle -> Z[k] for k = t+64h (registers), then stage 0 -> A.
    float zkr[4], zki[4];
#pragma unroll
    for (int h = 0; h < 4; ++h) {
        int k = t + 64 * h;
        float Arv = Br[g][k],       Aiv = Bi[g][k];
        float Crv = Br[g][256 - k], Civ = Bi[g][256 - k];
        float Xer = 0.5f * (Arv + Crv), Xei = 0.5f * (Aiv - Civ);
        float Dr  = 0.5f * (Arv - Crv), Di  = 0.5f * (Aiv + Civ);
        float c = twc[k], s = -tws[k];            // e^{+i*pi*k/256}
        float Xor = Dr * c - Di * s;
        float Xoi = Dr * s + Di * c;
        zkr[h] = (Xer - Xoi) * (1.f / 256.f);
        zki[h] = (Xei + Xor) * (1.f / 256.f);
    }
    {
        float t0r = zkr[0] + zkr[2], t0i = zki[0] + zki[2];
        float t1r = zkr[0] - zkr[2], t1i = zki[0] - zki[2];
        float t2r = zkr[1] + zkr[3], t2i = zki[1] + zki[3];
        float t3r = zkr[1] - zkr[3], t3i = zki[1] - zki[3];
        float y0r = t0r + t2r, y0i = t0i + t2i;
        float u1r = t1r - t3i, u1i = t1i + t3r;   // inverse orientation
        float u2r = t0r - t2r, u2i = t0i - t2i;
        float u3r = t1r + t3i, u3i = t1i - t3r;
        float w1c = twc[2 * t], w1s = -tws[2 * t];
        float w2c = w1c*w1c - w1s*w1s, w2s = 2.f*w1c*w1s;
        float w3c = w2c*w1c - w2s*w1s, w3s = w2c*w1s + w2s*w1c;
        int o = 4 * t;
        Ar[g][SP(o)]   = y0r;                  Ai[g][SP(o)]   = y0i;
        Ar[g][SP(o+1)] = u1r*w1c - u1i*w1s;    Ai[g][SP(o+1)] = u1r*w1s + u1i*w1c;
        Ar[g][SP(o+2)] = u2r*w2c - u2i*w2s;    Ai[g][SP(o+2)] = u2r*w2s + u2i*w2c;
        Ar[g][SP(o+3)] = u3r*w3c - u3i*w3s;    Ai[g][SP(o+3)] = u3r*w3s + u3i*w3c;
    }
    __syncthreads();

    // Stages 1-2 (A->B->A), inverse twiddles.
#pragma unroll
    for (int r = 1; r < 3; ++r) {
        int m = 1 << (2 * r);
        int k = t & (m - 1);
        int j = t >> (2 * r);
        const float (*srcr)[264] = (r == 1) ? Ar : Br;
        const float (*srci)[264] = (r == 1) ? Ai : Bi;
        float (*dstr)[264] = (r == 1) ? Br : Ar;
        float (*dsti)[264] = (r == 1) ? Bi : Ai;
        float a0r = srcr[g][SP(t)],       a0i = srci[g][SP(t)];
        float a1r = srcr[g][SP(t + 64)],  a1i = srci[g][SP(t + 64)];
        float a2r = srcr[g][SP(t + 128)], a2i = srci[g][SP(t + 128)];
        float a3r = srcr[g][SP(t + 192)], a3i = srci[g][SP(t + 192)];
        float t0r = a0r + a2r, t0i = a0i + a2i;
        float t1r = a0r - a2r, t1i = a0i - a2i;
        float t2r = a1r + a3r, t2i = a1i + a3i;
        float t3r = a1r - a3r, t3i = a1i - a3i;
        float y0r = t0r + t2r, y0i = t0i + t2i;
        float u1r = t1r - t3i, u1i = t1i + t3r;
        float u2r = t0r - t2r, u2i = t0i - t2i;
        float u3r = t1r + t3i, u3i = t1i - t3r;
        int idx = 2 * j * m;
        float w1c = twc[idx], w1s = -tws[idx];
        float w2c = w1c*w1c - w1s*w1s, w2s = 2.f*w1c*w1s;
        float w3c = w2c*w1c - w2s*w1s, w3s = w2c*w1s + w2s*w1c;
        int o = 4 * m * j + k;
        dstr[g][SP(o)]       = y0r;                  dsti[g][SP(o)]       = y0i;
        dstr[g][SP(o+m)]     = u1r*w1c - u1i*w1s;    dsti[g][SP(o+m)]     = u1r*w1s + u1i*w1c;
        dstr[g][SP(o+2*m)]   = u2r*w2c - u2i*w2s;    dsti[g][SP(o+2*m)]   = u2r*w2s + u2i*w2c;
        dstr[g][SP(o+3*m)]   = u3r*w3c - u3i*w3s;    dsti[g][SP(o+3*m)]   = u3r*w3s + u3i*w3c;
        __syncthreads();
    }

    // Stage 3 (twiddle-free) -> x[2n]+i*x[2n+1] at n = t+64h -> global.
    {
        float a0r = Ar[g][SP(t)],       a0i = Ai[g][SP(t)];
        float a1r = Ar[g][SP(t + 64)],  a1i = Ai[g][SP(t + 64)];
        float a2r = Ar[g][SP(t + 128)], a2i = Ai[g][SP(t + 128)];
        float a3r = Ar[g][SP(t + 192)], a3i = Ai[g][SP(t + 192)];
        float t0r = a0r + a2r, t0i = a0i + a2i;
        float t1r = a0r - a2r, t1i = a0i - a2i;
        float t2r = a1r + a3r, t2i = a1i + a3i;
        float t3r = a1r - a3r, t3i = a1i - a3i;
        float2 v[4];
        v[0] = make_float2(t0r + t2r, t0i + t2i);
        v[1] = make_float2(t1r - t3i, t1i + t3r);
        v[2] = make_float2(t0r - t2r, t0i - t2i);
        v[3] = make_float2(t1r + t3i, t1i - t3r);
        size_t base = (size_t)f * 256;
        float2* o2 = (float2*)(out + base);
#pragma unroll
        for (int h = 0; h < 4; ++h) {
            int n = t + 64 * h;
            if (parity == 0) {
                o2[n] = v[h];
            } else if (base + 2 * (size_t)n + 1 < (size_t)PIANO) {
                float2 cur = o2[n];
                o2[n] = make_float2(cur.x + v[h].x, cur.y + v[h].y);
            }
        }
    }
}

// ---------------------------------------------------------------------------
extern "C" void kernel_launch(void* const* d_in, const int* in_sizes, int n_in,
                              void* d_out, int out_size) {
    const float* noise = nullptr;
    const float* env = nullptr;
    const float* tfr = nullptr;
    const float* tfi = nullptr;
    for (int i = 0; i < n_in; ++i) {
        if (in_sizes[i] == 16777216) noise = (const float*)d_in[i];          // [32768, 512]
        else if (in_sizes[i] == 32770) env = (const float*)d_in[i];          // [32770]
        else if (in_sizes[i] == 8421890) {                                   // [32770, 257] x2
            if (!tfr) tfr = (const float*)d_in[i];
            else      tfi = (const float*)d_in[i];
        }
    }
    float* out = (float*)d_out;

    tw_init_kernel<<<1, 288>>>();
    fwd_kernel<<<N_ITER / FPB, 256>>>(noise, env);
    recur_kernel<<<N_ITER / CHUNK, 288>>>(tfr, tfi);
    inv_kernel<<<N_ITER / (2 * FPB), 256>>>(out, 0);
    inv_kernel<<<N_ITER / (2 * FPB), 256>>>(out, 1);
}